// round 10
// baseline (speedup 1.0000x reference)
#include <cuda_runtime.h>
#include <cuda_bf16.h>
#include <stdint.h>

#define S_LEN   2048
#define BATCH   2
#define DMODEL  1024
#define NHEAD   16
#define DHEAD   64
#define MROWS   4096
#define BHEADS  32
#define NELEM   (MROWS*DMODEL)    // 4,194,304

// Scratch (device globals; no allocations allowed)
__device__ __nv_bfloat16 g_Qh[NELEM], g_Ql[NELEM];   // head layout [n][s][64], hi/lo
__device__ __nv_bfloat16 g_Kh[NELEM], g_Kl[NELEM];
__device__ __nv_bfloat16 g_Vh[NELEM], g_Vl[NELEM];
__device__ float g_ctx[NELEM];                        // ctx (s,b,D) fp32

// ---------------------------------------------------------------------------
__device__ __forceinline__ float fast_exp(float x) {
    float y = x * 1.4426950408889634f;
    y = fmaxf(y, -126.0f);
    float t = y + 12582912.0f;
    int   n = __float_as_int(t) - 0x4B400000;
    float f = y - (t - 12582912.0f);
    float p = 1.3333558146e-3f;
    p = fmaf(p, f, 9.6181291971e-3f);
    p = fmaf(p, f, 5.5504108664e-2f);
    p = fmaf(p, f, 2.4022650696e-1f);
    p = fmaf(p, f, 6.9314718056e-1f);
    p = fmaf(p, f, 1.0f);
    return __int_as_float(__float_as_int(p) + (n << 23));
}

__device__ __forceinline__ uint32_t b2u(__nv_bfloat162 v) {
    uint32_t u; memcpy(&u, &v, 4); return u;
}
__device__ __forceinline__ uint32_t split2(float x, float y, uint32_t& lo) {
    __nv_bfloat16 hx = __float2bfloat16_rn(x);
    __nv_bfloat16 hy = __float2bfloat16_rn(y);
    __nv_bfloat162 h; h.x = hx; h.y = hy;
    __nv_bfloat162 l = __floats2bfloat162_rn(x - __bfloat162float(hx),
                                             y - __bfloat162float(hy));
    lo = b2u(l);
    return b2u(h);
}
__device__ __forceinline__ void cvt_store(__nv_bfloat16* hb, __nv_bfloat16* lb, float4 v) {
    uint32_t l0, l1;
    uint32_t h0 = split2(v.x, v.y, l0);
    uint32_t h1 = split2(v.z, v.w, l1);
    ((uint32_t*)hb)[0] = h0; ((uint32_t*)hb)[1] = h1;
    ((uint32_t*)lb)[0] = l0; ((uint32_t*)lb)[1] = l1;
}

__device__ __forceinline__ void ldsm4(uint32_t* r, const __nv_bfloat16* p) {
    uint32_t a = (uint32_t)__cvta_generic_to_shared(p);
    asm volatile("ldmatrix.sync.aligned.m8n8.x4.shared.b16 {%0,%1,%2,%3}, [%4];"
        : "=r"(r[0]), "=r"(r[1]), "=r"(r[2]), "=r"(r[3]) : "r"(a));
}
__device__ __forceinline__ void ldsm4a(uint32_t* r, uint32_t a) {
    asm volatile("ldmatrix.sync.aligned.m8n8.x4.shared.b16 {%0,%1,%2,%3}, [%4];"
        : "=r"(r[0]), "=r"(r[1]), "=r"(r[2]), "=r"(r[3]) : "r"(a));
}
__device__ __forceinline__ void ldsm4ta(uint32_t* r, uint32_t a) {
    asm volatile("ldmatrix.sync.aligned.m8n8.x4.trans.shared.b16 {%0,%1,%2,%3}, [%4];"
        : "=r"(r[0]), "=r"(r[1]), "=r"(r[2]), "=r"(r[3]) : "r"(a));
}
__device__ __forceinline__ void mma16816(float* d, const uint32_t* a,
                                         uint32_t b0, uint32_t b1) {
    asm volatile(
        "mma.sync.aligned.m16n8k16.row.col.f32.bf16.bf16.f32 "
        "{%0,%1,%2,%3},{%4,%5,%6,%7},{%8,%9},{%0,%1,%2,%3};"
        : "+f"(d[0]), "+f"(d[1]), "+f"(d[2]), "+f"(d[3])
        : "r"(a[0]), "r"(a[1]), "r"(a[2]), "r"(a[3]), "r"(b0), "r"(b1));
}
__device__ __forceinline__ void cpa16(uint32_t dst, const void* src) {
    asm volatile("cp.async.cg.shared.global [%0], [%1], 16;\n" :: "r"(dst), "l"(src));
}
__device__ __forceinline__ void cp_commit() {
    asm volatile("cp.async.commit_group;\n");
}
template<int N> __device__ __forceinline__ void cp_wait() {
    asm volatile("cp.async.wait_group %0;\n" :: "n"(N));
}
__device__ __forceinline__ uint32_t aswz(uint32_t o) { return o ^ ((o >> 3) & 0x70); }

// ---------------------------------------------------------------------------
// GEMM: out = A(4096x1024) @ W^T + bias, bf16x3. Term-major MMA issue order
// (same-acc reuse distance 16 instead of 1). Per-acc term order unchanged
// => bit-identical results to the distance-1 version.
// ---------------------------------------------------------------------------
#define GST 40

__global__ void __launch_bounds__(256,2) gemm_mma(
    const float* __restrict__ A, const float* __restrict__ W,
    const float* __restrict__ bias, const float* __restrict__ resid,
    float* __restrict__ out, int mode)
{
    __shared__ __nv_bfloat16 sAh[128*GST], sAl[128*GST];
    __shared__ __nv_bfloat16 sBh[128*GST], sBl[128*GST];

    const int tid  = threadIdx.x;
    const int lane = tid & 31;
    const int wid  = tid >> 5;
    const int wm   = (wid >> 2) * 64;
    const int wn   = (wid & 3) * 32;
    const int row0 = blockIdx.y * 128;
    const int col0 = blockIdx.x * 128;
    const int lrow = lane & 15;
    const int lcol = (lane >> 4) * 8;

    const float* Ap = (mode >= 3) ? g_ctx : A;
    __nv_bfloat16 *Oh = (mode == 0) ? g_Qh : (mode == 1) ? g_Kh : g_Vh;
    __nv_bfloat16 *Ol = (mode == 0) ? g_Ql : (mode == 1) ? g_Kl : g_Vl;

    float acc[4][4][4] = {};

    const int lr = tid >> 3;          // 0..31
    const int lc = (tid & 7) * 4;     // 0..28

    // prefetch tile 0
    float4 av[4], bv[4];
    #pragma unroll
    for (int p = 0; p < 4; p++) {
        av[p] = *(const float4*)&Ap[(size_t)(row0 + lr + p*32) * DMODEL + lc];
        bv[p] = *(const float4*)&W [(size_t)(col0 + lr + p*32) * DMODEL + lc];
    }

    for (int k0 = 0; k0 < DMODEL; k0 += 32) {
        __syncthreads();
        #pragma unroll
        for (int p = 0; p < 4; p++) {
            int r = lr + p*32;
            cvt_store(&sAh[r*GST + lc], &sAl[r*GST + lc], av[p]);
            cvt_store(&sBh[r*GST + lc], &sBl[r*GST + lc], bv[p]);
        }
        __syncthreads();

        if (k0 + 32 < DMODEL) {
            #pragma unroll
            for (int p = 0; p < 4; p++) {
                av[p] = *(const float4*)&Ap[(size_t)(row0 + lr + p*32) * DMODEL + k0 + 32 + lc];
                bv[p] = *(const float4*)&W [(size_t)(col0 + lr + p*32) * DMODEL + k0 + 32 + lc];
            }
        }

        #pragma unroll
        for (int ks = 0; ks < 2; ks++) {
            uint32_t ah[4][4], al[4][4], bh[2][4], bl[2][4];
            #pragma unroll
            for (int im = 0; im < 4; im++) {
                int off = (wm + im*16 + lrow) * GST + ks*16 + lcol;
                ldsm4(ah[im], &sAh[off]);
                ldsm4(al[im], &sAl[off]);
            }
            #pragma unroll
            for (int g = 0; g < 2; g++) {
                int off = (wn + g*16 + lrow) * GST + ks*16 + lcol;
                ldsm4(bh[g], &sBh[off]);
                ldsm4(bl[g], &sBl[off]);
            }
            // term 1: Ah x Bh (all 16 accumulators)
            #pragma unroll
            for (int im = 0; im < 4; im++)
                #pragma unroll
                for (int jn = 0; jn < 4; jn++) {
                    int g = jn >> 1, o = jn & 1;
                    mma16816(acc[im][jn], ah[im], bh[g][o], bh[g][o+2]);
                }
            // term 2: Ah x Bl
            #pragma unroll
            for (int im = 0; im < 4; im++)
                #pragma unroll
                for (int jn = 0; jn < 4; jn++) {
                    int g = jn >> 1, o = jn & 1;
                    mma16816(acc[im][jn], ah[im], bl[g][o], bl[g][o+2]);
                }
            // term 3: Al x Bh
            #pragma unroll
            for (int im = 0; im < 4; im++)
                #pragma unroll
                for (int jn = 0; jn < 4; jn++) {
                    int g = jn >> 1, o = jn & 1;
                    mma16816(acc[im][jn], al[im], bh[g][o], bh[g][o+2]);
                }
        }
    }

    #pragma unroll
    for (int im = 0; im < 4; im++) {
        #pragma unroll
        for (int jn = 0; jn < 4; jn++) {
            int rg = row0 + wm + im * 16 + (lane >> 2);
            int cg = col0 + wn + jn * 8 + (lane & 3) * 2;
            float v0 = acc[im][jn][0] + bias[cg];
            float v1 = acc[im][jn][1] + bias[cg+1];
            float v2 = acc[im][jn][2] + bias[cg];
            float v3 = acc[im][jn][3] + bias[cg+1];
            if (mode < 3) {
                int s0 = rg >> 1, b0b = rg & 1;
                int s1 = (rg + 8) >> 1, b1b = (rg + 8) & 1;
                int h = cg >> 6, dj = cg & 63;
                size_t o0 = (((size_t)b0b * NHEAD + h) * S_LEN + s0) * DHEAD + dj;
                size_t o1 = (((size_t)b1b * NHEAD + h) * S_LEN + s1) * DHEAD + dj;
                uint32_t lo;
                uint32_t hi = split2(v0, v1, lo);
                *(uint32_t*)&Oh[o0] = hi; *(uint32_t*)&Ol[o0] = lo;
                hi = split2(v2, v3, lo);
                *(uint32_t*)&Oh[o1] = hi; *(uint32_t*)&Ol[o1] = lo;
            } else {
                const float* rr0 = &resid[(size_t)rg * DMODEL + cg];
                const float* rr1 = &resid[(size_t)(rg+8) * DMODEL + cg];
                *(float2*)&out[(size_t)rg * DMODEL + cg]     = make_float2(v0 + rr0[0], v1 + rr0[1]);
                *(float2*)&out[(size_t)(rg+8) * DMODEL + cg] = make_float2(v2 + rr1[0], v3 + rr1[1]);
            }
        }
    }
}

// ---------------------------------------------------------------------------
// Flash attention: bf16x3, 3-stage cp.async, online softmax, 2 CTAs/SM.
// MMA issue reordered term-major within each g (same-acc distance 1 -> 2),
// per-acc term order unchanged => bit-identical.
// ---------------------------------------------------------------------------
#define A_ARR   8192u
#define A_STAGE (4u*A_ARR)
#define ATTN_SMEM (3*A_STAGE)          // 98304
#define A_NT 32

__global__ void __launch_bounds__(256,2) attn_mma()
{
    extern __shared__ __nv_bfloat16 sa_mem[];
    const uint32_t smb = (uint32_t)__cvta_generic_to_shared(sa_mem);

    const int tid  = threadIdx.x;
    const int lane = tid & 31;
    const int wid  = tid >> 5;
    const int wm   = wid * 16;
    const int n    = blockIdx.y;
    const int q0   = blockIdx.x * 128;
    const int lrow = lane & 15;
    const int lcolb = ((lane >> 4) * 8) * 2;

    const size_t hofs = (size_t)n * S_LEN * DHEAD;
    const __nv_bfloat16* Qh_g = g_Qh + hofs;
    const __nv_bfloat16* Ql_g = g_Ql + hofs;
    const __nv_bfloat16* srcs[4] = {g_Kh + hofs, g_Kl + hofs, g_Vh + hofs, g_Vl + hofs};

    const int rw = tid >> 2;
    const int qc = tid & 3;

    // Q fragments in registers
    uint32_t qh[4][4], ql[4][4];
    {
        const int qr = q0 + wm + (lane >> 2);
        const int qcc = (lane & 3) * 2;
        #pragma unroll
        for (int kk = 0; kk < 4; kk++) {
            size_t b0 = (size_t)qr * DHEAD + kk * 16 + qcc;
            qh[kk][0] = *(const uint32_t*)&Qh_g[b0];
            qh[kk][1] = *(const uint32_t*)&Qh_g[b0 + 8*DHEAD];
            qh[kk][2] = *(const uint32_t*)&Qh_g[b0 + 8];
            qh[kk][3] = *(const uint32_t*)&Qh_g[b0 + 8*DHEAD + 8];
            ql[kk][0] = *(const uint32_t*)&Ql_g[b0];
            ql[kk][1] = *(const uint32_t*)&Ql_g[b0 + 8*DHEAD];
            ql[kk][2] = *(const uint32_t*)&Ql_g[b0 + 8];
            ql[kk][3] = *(const uint32_t*)&Ql_g[b0 + 8*DHEAD + 8];
        }
    }

    float ctx[8][4] = {};
    float m0 = -1e30f, m1 = -1e30f, l0 = 0.0f, l1 = 0.0f;

    // prologue: stages 0,1
    #pragma unroll
    for (int st = 0; st < 2; st++) {
        #pragma unroll
        for (int a = 0; a < 4; a++) {
            const __nv_bfloat16* p = srcs[a] + (size_t)(st * 64 + rw) * DHEAD;
            uint32_t ab = (uint32_t)st * A_STAGE + (uint32_t)a * A_ARR + (uint32_t)rw * 128;
            #pragma unroll
            for (int j = 0; j < 2; j++) {
                int c16 = qc * 2 + j;
                cpa16(smb + ab + (uint32_t)((c16 ^ (rw & 7)) * 16), p + c16 * 8);
            }
        }
        cp_commit();
    }

    for (int t = 0; t < A_NT; t++) {
        cp_wait<1>();
        __syncthreads();

        if (t + 2 < A_NT) {
            int st = t + 2, slot = st % 3;
            #pragma unroll
            for (int a = 0; a < 4; a++) {
                const __nv_bfloat16* p = srcs[a] + (size_t)(st * 64 + rw) * DHEAD;
                uint32_t ab = (uint32_t)slot * A_STAGE + (uint32_t)a * A_ARR + (uint32_t)rw * 128;
                #pragma unroll
                for (int j = 0; j < 2; j++) {
                    int c16 = qc * 2 + j;
                    cpa16(smb + ab + (uint32_t)((c16 ^ (rw & 7)) * 16), p + c16 * 8);
                }
            }
        }
        cp_commit();

        const uint32_t sb = smb + (uint32_t)(t % 3) * A_STAGE;

        // S = Q @ K^T  (term-major within g: acc reuse distance 2)
        float sa[8][4] = {};
        #pragma unroll
        for (int kk = 0; kk < 4; kk++) {
            #pragma unroll
            for (int g = 0; g < 4; g++) {
                uint32_t khf[4], klf[4];
                uint32_t o = (uint32_t)(g * 16 + lrow) * 128 + kk * 32 + lcolb;
                ldsm4a(khf, sb + 0 * A_ARR + aswz(o));
                ldsm4a(klf, sb + 1 * A_ARR + aswz(o));
                mma16816(sa[2*g+0], qh[kk], khf[0], khf[2]);
                mma16816(sa[2*g+1], qh[kk], khf[1], khf[3]);
                mma16816(sa[2*g+0], qh[kk], klf[0], klf[2]);
                mma16816(sa[2*g+1], qh[kk], klf[1], klf[3]);
                mma16816(sa[2*g+0], ql[kk], khf[0], khf[2]);
                mma16816(sa[2*g+1], ql[kk], khf[1], khf[3]);
            }
        }

        // Online softmax (REQUIRED for bf16x3 precision: keeps P in [0,1])
        float mx0 = -1e30f, mx1 = -1e30f;
        #pragma unroll
        for (int jn = 0; jn < 8; jn++) {
            mx0 = fmaxf(mx0, fmaxf(sa[jn][0], sa[jn][1]));
            mx1 = fmaxf(mx1, fmaxf(sa[jn][2], sa[jn][3]));
        }
        mx0 = fmaxf(mx0, __shfl_xor_sync(0xffffffffu, mx0, 1));
        mx0 = fmaxf(mx0, __shfl_xor_sync(0xffffffffu, mx0, 2));
        mx1 = fmaxf(mx1, __shfl_xor_sync(0xffffffffu, mx1, 1));
        mx1 = fmaxf(mx1, __shfl_xor_sync(0xffffffffu, mx1, 2));

        float mn0 = fmaxf(m0, mx0), mn1 = fmaxf(m1, mx1);
        float c0 = fast_exp(m0 - mn0), c1 = fast_exp(m1 - mn1);
        float s0 = 0.0f, s1 = 0.0f;
        #pragma unroll
        for (int jn = 0; jn < 8; jn++) {
            sa[jn][0] = fast_exp(sa[jn][0] - mn0);
            sa[jn][1] = fast_exp(sa[jn][1] - mn0);
            sa[jn][2] = fast_exp(sa[jn][2] - mn1);
            sa[jn][3] = fast_exp(sa[jn][3] - mn1);
            s0 += sa[jn][0] + sa[jn][1];
            s1 += sa[jn][2] + sa[jn][3];
            ctx[jn][0] *= c0; ctx[jn][1] *= c0;
            ctx[jn][2] *= c1; ctx[jn][3] *= c1;
        }
        s0 += __shfl_xor_sync(0xffffffffu, s0, 1);
        s0 += __shfl_xor_sync(0xffffffffu, s0, 2);
        s1 += __shfl_xor_sync(0xffffffffu, s1, 1);
        s1 += __shfl_xor_sync(0xffffffffu, s1, 2);
        l0 = l0 * c0 + s0;  m0 = mn0;
        l1 = l1 * c1 + s1;  m1 = mn1;

        // Pack P fragments (QK acc layout == PV A-frag layout)
        uint32_t ph[4][4], pl[4][4];
        #pragma unroll
        for (int kc = 0; kc < 4; kc++) {
            ph[kc][0] = split2(sa[2*kc][0],   sa[2*kc][1],   pl[kc][0]);
            ph[kc][1] = split2(sa[2*kc][2],   sa[2*kc][3],   pl[kc][1]);
            ph[kc][2] = split2(sa[2*kc+1][0], sa[2*kc+1][1], pl[kc][2]);
            ph[kc][3] = split2(sa[2*kc+1][2], sa[2*kc+1][3], pl[kc][3]);
        }

        // ctx += P @ V  (term-major within g: acc reuse distance 2)
        #pragma unroll
        for (int kc = 0; kc < 4; kc++) {
            #pragma unroll
            for (int g = 0; g < 4; g++) {
                uint32_t vhf[4], vlf[4];
                uint32_t o = (uint32_t)(kc * 16 + lrow) * 128 + g * 32 + lcolb;
                ldsm4ta(vhf, sb + 2 * A_ARR + aswz(o));
                ldsm4ta(vlf, sb + 3 * A_ARR + aswz(o));
                mma16816(ctx[2*g+0], ph[kc], vhf[0], vhf[1]);
                mma16816(ctx[2*g+1], ph[kc], vhf[2], vhf[3]);
                mma16816(ctx[2*g+0], ph[kc], vlf[0], vlf[1]);
                mma16816(ctx[2*g+1], ph[kc], vlf[2], vlf[3]);
                mma16816(ctx[2*g+0], pl[kc], vhf[0], vhf[1]);
                mma16816(ctx[2*g+1], pl[kc], vhf[2], vhf[3]);
            }
        }
    }

    // Finalize: write fp32 ctx (s,b,D)
    const int b = n >> 4, h = n & 15;
    const float inv0 = 1.0f / l0, inv1 = 1.0f / l1;
    const int s0r = q0 + wm + (lane >> 2);
    #pragma unroll
    for (int jn = 0; jn < 8; jn++) {
        int dh = jn * 8 + (lane & 3) * 2;
        size_t o0 = ((size_t)s0r * BATCH + b) * DMODEL + h * DHEAD + dh;
        size_t o1 = ((size_t)(s0r + 8) * BATCH + b) * DMODEL + h * DHEAD + dh;
        *(float2*)&g_ctx[o0] = make_float2(ctx[jn][0] * inv0, ctx[jn][1] * inv0);
        *(float2*)&g_ctx[o1] = make_float2(ctx[jn][2] * inv1, ctx[jn][3] * inv1);
    }
}

// ---------------------------------------------------------------------------
// LayerNorm (in-place): one block per row of 1024
// ---------------------------------------------------------------------------
__device__ __forceinline__ float block_sum256(float v, float* red)
{
    #pragma unroll
    for (int o = 16; o > 0; o >>= 1) v += __shfl_xor_sync(0xffffffffu, v, o);
    if ((threadIdx.x & 31) == 0) red[threadIdx.x >> 5] = v;
    __syncthreads();
    if (threadIdx.x < 32) {
        float x = (threadIdx.x < 8) ? red[threadIdx.x] : 0.0f;
        #pragma unroll
        for (int o = 4; o > 0; o >>= 1) x += __shfl_xor_sync(0xffffffffu, x, o);
        if (threadIdx.x == 0) red[0] = x;
    }
    __syncthreads();
    float rv = red[0];
    __syncthreads();
    return rv;
}

__global__ void __launch_bounds__(256) ln_kernel(
    float* __restrict__ y, const float* __restrict__ w, const float* __restrict__ bb)
{
    __shared__ float red[8];
    const int rix = blockIdx.x;
    float* row = y + (size_t)rix * DMODEL;
    const int tid = threadIdx.x;

    float v[4];
    #pragma unroll
    for (int p = 0; p < 4; p++) v[p] = row[tid + p * 256];

    float s = v[0] + v[1] + v[2] + v[3];
    float mean = block_sum256(s, red) * (1.0f / DMODEL);

    float ss = 0.0f;
    #pragma unroll
    for (int p = 0; p < 4; p++) { float d = v[p] - mean; ss = fmaf(d, d, ss); }
    float var = block_sum256(ss, red) * (1.0f / DMODEL);
    float rstd = rsqrtf(var + 1e-12f);

    #pragma unroll
    for (int p = 0; p < 4; p++) {
        int c = tid + p * 256;
        row[c] = w[c] * (v[p] - mean) * rstd + bb[c];
    }
}

// ---------------------------------------------------------------------------
extern "C" void kernel_launch(void* const* d_in, const int* in_sizes, int n_in,
                              void* d_out, int out_size)
{
    const float* q_in = (const float*)d_in[0];
    const float* k_in = (const float*)d_in[1];
    const float* v_in = (const float*)d_in[2];
    const float* Wq   = (const float*)d_in[3];
    const float* bq   = (const float*)d_in[4];
    const float* Wk   = (const float*)d_in[5];
    const float* bk   = (const float*)d_in[6];
    const float* Wv   = (const float*)d_in[7];
    const float* bv   = (const float*)d_in[8];
    const float* Wo   = (const float*)d_in[9];
    const float* bo   = (const float*)d_in[10];
    const float* ln_w = (const float*)d_in[11];
    const float* ln_b = (const float*)d_in[12];
    float* out = (float*)d_out;

    static int attr_done = 0;
    if (!attr_done) {
        cudaFuncSetAttribute(attn_mma, cudaFuncAttributeMaxDynamicSharedMemorySize, ATTN_SMEM);
        attr_done = 1;
    }

    dim3 gg(DMODEL / 128, MROWS / 128);   // (8, 32)

    gemm_mma<<<gg, 256>>>(q_in, Wq, bq, nullptr, nullptr, 0);
    gemm_mma<<<gg, 256>>>(k_in, Wk, bk, nullptr, nullptr, 1);
    gemm_mma<<<gg, 256>>>(v_in, Wv, bv, nullptr, nullptr, 2);

    attn_mma<<<dim3(S_LEN / 128, BHEADS), 256, ATTN_SMEM>>>();

    gemm_mma<<<gg, 256>>>(nullptr, Wo, bo, q_in, out, 3);

    ln_kernel<<<MROWS, 256>>>(out, ln_w, ln_b);
}

// round 11
// speedup vs baseline: 1.0743x; 1.0743x over previous
#include <cuda_runtime.h>
#include <cuda_bf16.h>
#include <stdint.h>

#define S_LEN   2048
#define BATCH   2
#define DMODEL  1024
#define NHEAD   16
#define DHEAD   64
#define MROWS   4096
#define BHEADS  32
#define NELEM   (MROWS*DMODEL)    // 4,194,304

// Scratch (device globals; no allocations allowed)
__device__ __nv_bfloat16 g_Qh[NELEM], g_Ql[NELEM];   // head layout [n][s][64], hi/lo
__device__ __nv_bfloat16 g_Kh[NELEM], g_Kl[NELEM];
__device__ __nv_bfloat16 g_Vh[NELEM], g_Vl[NELEM];
__device__ float g_ctx[NELEM];                        // ctx (s,b,D) fp32

// ---------------------------------------------------------------------------
__device__ __forceinline__ uint32_t b2u(__nv_bfloat162 v) {
    uint32_t u; memcpy(&u, &v, 4); return u;
}
__device__ __forceinline__ uint32_t split2(float x, float y, uint32_t& lo) {
    __nv_bfloat16 hx = __float2bfloat16_rn(x);
    __nv_bfloat16 hy = __float2bfloat16_rn(y);
    __nv_bfloat162 h; h.x = hx; h.y = hy;
    __nv_bfloat162 l = __floats2bfloat162_rn(x - __bfloat162float(hx),
                                             y - __bfloat162float(hy));
    lo = b2u(l);
    return b2u(h);
}
__device__ __forceinline__ void cvt_store(__nv_bfloat16* hb, __nv_bfloat16* lb, float4 v) {
    uint32_t l0, l1;
    uint32_t h0 = split2(v.x, v.y, l0);
    uint32_t h1 = split2(v.z, v.w, l1);
    ((uint32_t*)hb)[0] = h0; ((uint32_t*)hb)[1] = h1;
    ((uint32_t*)lb)[0] = l0; ((uint32_t*)lb)[1] = l1;
}

__device__ __forceinline__ void ldsm4(uint32_t* r, const __nv_bfloat16* p) {
    uint32_t a = (uint32_t)__cvta_generic_to_shared(p);
    asm volatile("ldmatrix.sync.aligned.m8n8.x4.shared.b16 {%0,%1,%2,%3}, [%4];"
        : "=r"(r[0]), "=r"(r[1]), "=r"(r[2]), "=r"(r[3]) : "r"(a));
}
__device__ __forceinline__ void ldsm4a(uint32_t* r, uint32_t a) {
    asm volatile("ldmatrix.sync.aligned.m8n8.x4.shared.b16 {%0,%1,%2,%3}, [%4];"
        : "=r"(r[0]), "=r"(r[1]), "=r"(r[2]), "=r"(r[3]) : "r"(a));
}
__device__ __forceinline__ void ldsm4ta(uint32_t* r, uint32_t a) {
    asm volatile("ldmatrix.sync.aligned.m8n8.x4.trans.shared.b16 {%0,%1,%2,%3}, [%4];"
        : "=r"(r[0]), "=r"(r[1]), "=r"(r[2]), "=r"(r[3]) : "r"(a));
}
__device__ __forceinline__ void mma16816(float* d, const uint32_t* a,
                                         uint32_t b0, uint32_t b1) {
    asm volatile(
        "mma.sync.aligned.m16n8k16.row.col.f32.bf16.bf16.f32 "
        "{%0,%1,%2,%3},{%4,%5,%6,%7},{%8,%9},{%0,%1,%2,%3};"
        : "+f"(d[0]), "+f"(d[1]), "+f"(d[2]), "+f"(d[3])
        : "r"(a[0]), "r"(a[1]), "r"(a[2]), "r"(a[3]), "r"(b0), "r"(b1));
}
__device__ __forceinline__ void cpa16(uint32_t dst, const void* src) {
    asm volatile("cp.async.cg.shared.global [%0], [%1], 16;\n" :: "r"(dst), "l"(src));
}
__device__ __forceinline__ void cp_commit() {
    asm volatile("cp.async.commit_group;\n");
}
template<int N> __device__ __forceinline__ void cp_wait() {
    asm volatile("cp.async.wait_group %0;\n" :: "n"(N));
}
__device__ __forceinline__ uint32_t aswz(uint32_t o) { return o ^ ((o >> 3) & 0x70); }

// ---------------------------------------------------------------------------
// GEMM (R2/R9 measured-best): out = A(4096x1024) @ W^T + bias, bf16x3.
// fp32 global loads + register prefetch, in-kernel hi/lo split to smem.
// Block 128x128, BK=32, 8 warps (2x4), warp tile 64x32. GST=40 padded rows.
// mode 0/1/2: write split hi/lo Q/K/V head layout. mode 3: A=g_ctx, +resid.
// ---------------------------------------------------------------------------
#define GST 40

__global__ void __launch_bounds__(256) gemm_mma(
    const float* __restrict__ A, const float* __restrict__ W,
    const float* __restrict__ bias, const float* __restrict__ resid,
    float* __restrict__ out, int mode)
{
    __shared__ __nv_bfloat16 sAh[128*GST], sAl[128*GST];
    __shared__ __nv_bfloat16 sBh[128*GST], sBl[128*GST];

    const int tid  = threadIdx.x;
    const int lane = tid & 31;
    const int wid  = tid >> 5;
    const int wm   = (wid >> 2) * 64;
    const int wn   = (wid & 3) * 32;
    const int row0 = blockIdx.y * 128;
    const int col0 = blockIdx.x * 128;
    const int lrow = lane & 15;
    const int lcol = (lane >> 4) * 8;

    const float* Ap = (mode >= 3) ? g_ctx : A;
    __nv_bfloat16 *Oh = (mode == 0) ? g_Qh : (mode == 1) ? g_Kh : g_Vh;
    __nv_bfloat16 *Ol = (mode == 0) ? g_Ql : (mode == 1) ? g_Kl : g_Vl;

    float acc[4][4][4] = {};

    const int lr = tid >> 3;          // 0..31
    const int lc = (tid & 7) * 4;     // 0..28

    // prefetch tile 0
    float4 av[4], bv[4];
    #pragma unroll
    for (int p = 0; p < 4; p++) {
        av[p] = *(const float4*)&Ap[(size_t)(row0 + lr + p*32) * DMODEL + lc];
        bv[p] = *(const float4*)&W [(size_t)(col0 + lr + p*32) * DMODEL + lc];
    }

    for (int k0 = 0; k0 < DMODEL; k0 += 32) {
        __syncthreads();
        #pragma unroll
        for (int p = 0; p < 4; p++) {
            int r = lr + p*32;
            cvt_store(&sAh[r*GST + lc], &sAl[r*GST + lc], av[p]);
            cvt_store(&sBh[r*GST + lc], &sBl[r*GST + lc], bv[p]);
        }
        __syncthreads();

        if (k0 + 32 < DMODEL) {
            #pragma unroll
            for (int p = 0; p < 4; p++) {
                av[p] = *(const float4*)&Ap[(size_t)(row0 + lr + p*32) * DMODEL + k0 + 32 + lc];
                bv[p] = *(const float4*)&W [(size_t)(col0 + lr + p*32) * DMODEL + k0 + 32 + lc];
            }
        }

        #pragma unroll
        for (int ks = 0; ks < 2; ks++) {
            uint32_t ah[4][4], al[4][4], bh[2][4], bl[2][4];
            #pragma unroll
            for (int im = 0; im < 4; im++) {
                int off = (wm + im*16 + lrow) * GST + ks*16 + lcol;
                ldsm4(ah[im], &sAh[off]);
                ldsm4(al[im], &sAl[off]);
            }
            #pragma unroll
            for (int g = 0; g < 2; g++) {
                int off = (wn + g*16 + lrow) * GST + ks*16 + lcol;
                ldsm4(bh[g], &sBh[off]);
                ldsm4(bl[g], &sBl[off]);
            }
            #pragma unroll
            for (int im = 0; im < 4; im++)
                #pragma unroll
                for (int jn = 0; jn < 4; jn++) {
                    int g = jn >> 1, o = jn & 1;
                    mma16816(acc[im][jn], ah[im], bh[g][o], bh[g][o+2]);
                    mma16816(acc[im][jn], ah[im], bl[g][o], bl[g][o+2]);
                    mma16816(acc[im][jn], al[im], bh[g][o], bh[g][o+2]);
                }
        }
    }

    #pragma unroll
    for (int im = 0; im < 4; im++) {
        #pragma unroll
        for (int jn = 0; jn < 4; jn++) {
            int rg = row0 + wm + im * 16 + (lane >> 2);
            int cg = col0 + wn + jn * 8 + (lane & 3) * 2;
            float v0 = acc[im][jn][0] + bias[cg];
            float v1 = acc[im][jn][1] + bias[cg+1];
            float v2 = acc[im][jn][2] + bias[cg];
            float v3 = acc[im][jn][3] + bias[cg+1];
            if (mode < 3) {
                int s0 = rg >> 1, b0b = rg & 1;
                int s1 = (rg + 8) >> 1, b1b = (rg + 8) & 1;
                int h = cg >> 6, dj = cg & 63;
                size_t o0 = (((size_t)b0b * NHEAD + h) * S_LEN + s0) * DHEAD + dj;
                size_t o1 = (((size_t)b1b * NHEAD + h) * S_LEN + s1) * DHEAD + dj;
                uint32_t lo;
                uint32_t hi = split2(v0, v1, lo);
                *(uint32_t*)&Oh[o0] = hi; *(uint32_t*)&Ol[o0] = lo;
                hi = split2(v2, v3, lo);
                *(uint32_t*)&Oh[o1] = hi; *(uint32_t*)&Ol[o1] = lo;
            } else {
                const float* rr0 = &resid[(size_t)rg * DMODEL + cg];
                const float* rr1 = &resid[(size_t)(rg+8) * DMODEL + cg];
                *(float2*)&out[(size_t)rg * DMODEL + cg]     = make_float2(v0 + rr0[0], v1 + rr0[1]);
                *(float2*)&out[(size_t)(rg+8) * DMODEL + cg] = make_float2(v2 + rr1[0], v3 + rr1[1]);
            }
        }
    }
}

// ---------------------------------------------------------------------------
// Flash attention (R9 structure): bf16x3, 3-stage cp.async KV pipeline, one
// sync per tile, Q frags in registers, online softmax, 2 CTAs/SM.
// CHANGE vs R9: softmax exps use __expf (MUFU pipe, 2 issue slots) instead of
// fast_exp (10 FMA-pipe slots) — shrinks the serial softmax window between
// the QK and PV MMA phases where the tensor pipe idles.
// ---------------------------------------------------------------------------
#define A_ARR   8192u
#define A_STAGE (4u*A_ARR)
#define ATTN_SMEM (3*A_STAGE)          // 98304
#define A_NT 32

__global__ void __launch_bounds__(256,2) attn_mma()
{
    extern __shared__ __nv_bfloat16 sa_mem[];
    const uint32_t smb = (uint32_t)__cvta_generic_to_shared(sa_mem);

    const int tid  = threadIdx.x;
    const int lane = tid & 31;
    const int wid  = tid >> 5;
    const int wm   = wid * 16;
    const int n    = blockIdx.y;
    const int q0   = blockIdx.x * 128;
    const int lrow = lane & 15;
    const int lcolb = ((lane >> 4) * 8) * 2;

    const size_t hofs = (size_t)n * S_LEN * DHEAD;
    const __nv_bfloat16* Qh_g = g_Qh + hofs;
    const __nv_bfloat16* Ql_g = g_Ql + hofs;
    const __nv_bfloat16* srcs[4] = {g_Kh + hofs, g_Kl + hofs, g_Vh + hofs, g_Vl + hofs};

    const int rw = tid >> 2;
    const int qc = tid & 3;

    // Q fragments in registers
    uint32_t qh[4][4], ql[4][4];
    {
        const int qr = q0 + wm + (lane >> 2);
        const int qcc = (lane & 3) * 2;
        #pragma unroll
        for (int kk = 0; kk < 4; kk++) {
            size_t b0 = (size_t)qr * DHEAD + kk * 16 + qcc;
            qh[kk][0] = *(const uint32_t*)&Qh_g[b0];
            qh[kk][1] = *(const uint32_t*)&Qh_g[b0 + 8*DHEAD];
            qh[kk][2] = *(const uint32_t*)&Qh_g[b0 + 8];
            qh[kk][3] = *(const uint32_t*)&Qh_g[b0 + 8*DHEAD + 8];
            ql[kk][0] = *(const uint32_t*)&Ql_g[b0];
            ql[kk][1] = *(const uint32_t*)&Ql_g[b0 + 8*DHEAD];
            ql[kk][2] = *(const uint32_t*)&Ql_g[b0 + 8];
            ql[kk][3] = *(const uint32_t*)&Ql_g[b0 + 8*DHEAD + 8];
        }
    }

    float ctx[8][4] = {};
    float m0 = -1e30f, m1 = -1e30f, l0 = 0.0f, l1 = 0.0f;

    // prologue: stages 0,1
    #pragma unroll
    for (int st = 0; st < 2; st++) {
        #pragma unroll
        for (int a = 0; a < 4; a++) {
            const __nv_bfloat16* p = srcs[a] + (size_t)(st * 64 + rw) * DHEAD;
            uint32_t ab = (uint32_t)st * A_STAGE + (uint32_t)a * A_ARR + (uint32_t)rw * 128;
            #pragma unroll
            for (int j = 0; j < 2; j++) {
                int c16 = qc * 2 + j;
                cpa16(smb + ab + (uint32_t)((c16 ^ (rw & 7)) * 16), p + c16 * 8);
            }
        }
        cp_commit();
    }

    for (int t = 0; t < A_NT; t++) {
        cp_wait<1>();
        __syncthreads();

        if (t + 2 < A_NT) {
            int st = t + 2, slot = st % 3;
            #pragma unroll
            for (int a = 0; a < 4; a++) {
                const __nv_bfloat16* p = srcs[a] + (size_t)(st * 64 + rw) * DHEAD;
                uint32_t ab = (uint32_t)slot * A_STAGE + (uint32_t)a * A_ARR + (uint32_t)rw * 128;
                #pragma unroll
                for (int j = 0; j < 2; j++) {
                    int c16 = qc * 2 + j;
                    cpa16(smb + ab + (uint32_t)((c16 ^ (rw & 7)) * 16), p + c16 * 8);
                }
            }
        }
        cp_commit();

        const uint32_t sb = smb + (uint32_t)(t % 3) * A_STAGE;

        // S = Q @ K^T
        float sa[8][4] = {};
        #pragma unroll
        for (int kk = 0; kk < 4; kk++) {
            #pragma unroll
            for (int g = 0; g < 4; g++) {
                uint32_t khf[4], klf[4];
                uint32_t o = (uint32_t)(g * 16 + lrow) * 128 + kk * 32 + lcolb;
                ldsm4a(khf, sb + 0 * A_ARR + aswz(o));
                ldsm4a(klf, sb + 1 * A_ARR + aswz(o));
                #pragma unroll
                for (int o2 = 0; o2 < 2; o2++) {
                    mma16816(sa[2*g+o2], qh[kk], khf[o2], khf[o2+2]);
                    mma16816(sa[2*g+o2], qh[kk], klf[o2], klf[o2+2]);
                    mma16816(sa[2*g+o2], ql[kk], khf[o2], khf[o2+2]);
                }
            }
        }

        // Online softmax (exp on MUFU pipe via __expf)
        float mx0 = -1e30f, mx1 = -1e30f;
        #pragma unroll
        for (int jn = 0; jn < 8; jn++) {
            mx0 = fmaxf(mx0, fmaxf(sa[jn][0], sa[jn][1]));
            mx1 = fmaxf(mx1, fmaxf(sa[jn][2], sa[jn][3]));
        }
        mx0 = fmaxf(mx0, __shfl_xor_sync(0xffffffffu, mx0, 1));
        mx0 = fmaxf(mx0, __shfl_xor_sync(0xffffffffu, mx0, 2));
        mx1 = fmaxf(mx1, __shfl_xor_sync(0xffffffffu, mx1, 1));
        mx1 = fmaxf(mx1, __shfl_xor_sync(0xffffffffu, mx1, 2));

        float mn0 = fmaxf(m0, mx0), mn1 = fmaxf(m1, mx1);
        float c0 = __expf(m0 - mn0), c1 = __expf(m1 - mn1);
        float s0 = 0.0f, s1 = 0.0f;
        #pragma unroll
        for (int jn = 0; jn < 8; jn++) {
            sa[jn][0] = __expf(sa[jn][0] - mn0);
            sa[jn][1] = __expf(sa[jn][1] - mn0);
            sa[jn][2] = __expf(sa[jn][2] - mn1);
            sa[jn][3] = __expf(sa[jn][3] - mn1);
            s0 += sa[jn][0] + sa[jn][1];
            s1 += sa[jn][2] + sa[jn][3];
            ctx[jn][0] *= c0; ctx[jn][1] *= c0;
            ctx[jn][2] *= c1; ctx[jn][3] *= c1;
        }
        s0 += __shfl_xor_sync(0xffffffffu, s0, 1);
        s0 += __shfl_xor_sync(0xffffffffu, s0, 2);
        s1 += __shfl_xor_sync(0xffffffffu, s1, 1);
        s1 += __shfl_xor_sync(0xffffffffu, s1, 2);
        l0 = l0 * c0 + s0;  m0 = mn0;
        l1 = l1 * c1 + s1;  m1 = mn1;

        // Pack P fragments (QK acc layout == PV A-frag layout)
        uint32_t ph[4][4], pl[4][4];
        #pragma unroll
        for (int kc = 0; kc < 4; kc++) {
            ph[kc][0] = split2(sa[2*kc][0],   sa[2*kc][1],   pl[kc][0]);
            ph[kc][1] = split2(sa[2*kc][2],   sa[2*kc][3],   pl[kc][1]);
            ph[kc][2] = split2(sa[2*kc+1][0], sa[2*kc+1][1], pl[kc][2]);
            ph[kc][3] = split2(sa[2*kc+1][2], sa[2*kc+1][3], pl[kc][3]);
        }

        // ctx += P @ V   (V natural [kv][dh] via ldsm.trans)
        #pragma unroll
        for (int kc = 0; kc < 4; kc++) {
            #pragma unroll
            for (int g = 0; g < 4; g++) {
                uint32_t vhf[4], vlf[4];
                uint32_t o = (uint32_t)(kc * 16 + lrow) * 128 + g * 32 + lcolb;
                ldsm4ta(vhf, sb + 2 * A_ARR + aswz(o));
                ldsm4ta(vlf, sb + 3 * A_ARR + aswz(o));
                #pragma unroll
                for (int o2 = 0; o2 < 2; o2++) {
                    mma16816(ctx[2*g+o2], ph[kc], vhf[2*o2], vhf[2*o2+1]);
                    mma16816(ctx[2*g+o2], ph[kc], vlf[2*o2], vlf[2*o2+1]);
                    mma16816(ctx[2*g+o2], pl[kc], vhf[2*o2], vhf[2*o2+1]);
                }
            }
        }
    }

    // Finalize: write fp32 ctx (s,b,D)
    const int b = n >> 4, h = n & 15;
    const float inv0 = 1.0f / l0, inv1 = 1.0f / l1;
    const int s0r = q0 + wm + (lane >> 2);
    #pragma unroll
    for (int jn = 0; jn < 8; jn++) {
        int dh = jn * 8 + (lane & 3) * 2;
        size_t o0 = ((size_t)s0r * BATCH + b) * DMODEL + h * DHEAD + dh;
        size_t o1 = ((size_t)(s0r + 8) * BATCH + b) * DMODEL + h * DHEAD + dh;
        *(float2*)&g_ctx[o0] = make_float2(ctx[jn][0] * inv0, ctx[jn][1] * inv0);
        *(float2*)&g_ctx[o1] = make_float2(ctx[jn][2] * inv1, ctx[jn][3] * inv1);
    }
}

// ---------------------------------------------------------------------------
// LayerNorm (in-place): one block per row of 1024
// ---------------------------------------------------------------------------
__device__ __forceinline__ float block_sum256(float v, float* red)
{
    #pragma unroll
    for (int o = 16; o > 0; o >>= 1) v += __shfl_xor_sync(0xffffffffu, v, o);
    if ((threadIdx.x & 31) == 0) red[threadIdx.x >> 5] = v;
    __syncthreads();
    if (threadIdx.x < 32) {
        float x = (threadIdx.x < 8) ? red[threadIdx.x] : 0.0f;
        #pragma unroll
        for (int o = 4; o > 0; o >>= 1) x += __shfl_xor_sync(0xffffffffu, x, o);
        if (threadIdx.x == 0) red[0] = x;
    }
    __syncthreads();
    float rv = red[0];
    __syncthreads();
    return rv;
}

__global__ void __launch_bounds__(256) ln_kernel(
    float* __restrict__ y, const float* __restrict__ w, const float* __restrict__ bb)
{
    __shared__ float red[8];
    const int rix = blockIdx.x;
    float* row = y + (size_t)rix * DMODEL;
    const int tid = threadIdx.x;

    float v[4];
    #pragma unroll
    for (int p = 0; p < 4; p++) v[p] = row[tid + p * 256];

    float s = v[0] + v[1] + v[2] + v[3];
    float mean = block_sum256(s, red) * (1.0f / DMODEL);

    float ss = 0.0f;
    #pragma unroll
    for (int p = 0; p < 4; p++) { float d = v[p] - mean; ss = fmaf(d, d, ss); }
    float var = block_sum256(ss, red) * (1.0f / DMODEL);
    float rstd = rsqrtf(var + 1e-12f);

    #pragma unroll
    for (int p = 0; p < 4; p++) {
        int c = tid + p * 256;
        row[c] = w[c] * (v[p] - mean) * rstd + bb[c];
    }
}

// ---------------------------------------------------------------------------
extern "C" void kernel_launch(void* const* d_in, const int* in_sizes, int n_in,
                              void* d_out, int out_size)
{
    const float* q_in = (const float*)d_in[0];
    const float* k_in = (const float*)d_in[1];
    const float* v_in = (const float*)d_in[2];
    const float* Wq   = (const float*)d_in[3];
    const float* bq   = (const float*)d_in[4];
    const float* Wk   = (const float*)d_in[5];
    const float* bk   = (const float*)d_in[6];
    const float* Wv   = (const float*)d_in[7];
    const float* bv   = (const float*)d_in[8];
    const float* Wo   = (const float*)d_in[9];
    const float* bo   = (const float*)d_in[10];
    const float* ln_w = (const float*)d_in[11];
    const float* ln_b = (const float*)d_in[12];
    float* out = (float*)d_out;

    static int attr_done = 0;
    if (!attr_done) {
        cudaFuncSetAttribute(attn_mma, cudaFuncAttributeMaxDynamicSharedMemorySize, ATTN_SMEM);
        attr_done = 1;
    }

    dim3 gg(DMODEL / 128, MROWS / 128);   // (8, 32)

    gemm_mma<<<gg, 256>>>(q_in, Wq, bq, nullptr, nullptr, 0);
    gemm_mma<<<gg, 256>>>(k_in, Wk, bk, nullptr, nullptr, 1);
    gemm_mma<<<gg, 256>>>(v_in, Wv, bv, nullptr, nullptr, 2);

    attn_mma<<<dim3(S_LEN / 128, BHEADS), 256, ATTN_SMEM>>>();

    gemm_mma<<<gg, 256>>>(nullptr, Wo, bo, q_in, out, 3);

    ln_kernel<<<MROWS, 256>>>(out, ln_w, ln_b);
}

// round 12
// speedup vs baseline: 1.1191x; 1.0416x over previous
#include <cuda_runtime.h>
#include <cuda_bf16.h>
#include <stdint.h>

#define S_LEN   2048
#define BATCH   2
#define DMODEL  1024
#define NHEAD   16
#define DHEAD   64
#define MROWS   4096
#define BHEADS  32
#define NELEM   (MROWS*DMODEL)    // 4,194,304
#define LOG2E   1.4426950408889634f

// Scratch (device globals; no allocations allowed)
__device__ __nv_bfloat16 g_Qh[NELEM], g_Ql[NELEM];   // head layout [n][s][64], hi/lo (pre-scaled by log2e)
__device__ __nv_bfloat16 g_Kh[NELEM], g_Kl[NELEM];
__device__ __nv_bfloat16 g_Vh[NELEM], g_Vl[NELEM];
__device__ float g_ctx[NELEM];                        // ctx (s,b,D) fp32

// ---------------------------------------------------------------------------
__device__ __forceinline__ float ex2f(float x) {
    float r;
    asm("ex2.approx.f32 %0, %1;" : "=f"(r) : "f"(x));
    return r;
}

// Truncation-based split: hi = high 16 bits of fp32 (PRMT pairs two), lo = x-hi.
// hi+lo represents x to ~2^-17 relative. Cheaper than RN split (~6 ops vs ~9).
__device__ __forceinline__ uint32_t split2t(float x, float y, uint32_t& lo) {
    uint32_t xb = __float_as_uint(x), yb = __float_as_uint(y);
    uint32_t hi;
    asm("prmt.b32 %0, %1, %2, 0x7632;" : "=r"(hi) : "r"(xb), "r"(yb));
    float hx = __uint_as_float(xb & 0xFFFF0000u);
    float hy = __uint_as_float(yb & 0xFFFF0000u);
    float lx = x - hx, ly = y - hy;
    uint32_t l;
    asm("cvt.rn.bf16x2.f32 %0, %1, %2;" : "=r"(l) : "f"(ly), "f"(lx));
    lo = l;
    return hi;
}
__device__ __forceinline__ void cvt_store(__nv_bfloat16* hb, __nv_bfloat16* lb, float4 v) {
    uint32_t l0, l1;
    uint32_t h0 = split2t(v.x, v.y, l0);
    uint32_t h1 = split2t(v.z, v.w, l1);
    ((uint32_t*)hb)[0] = h0; ((uint32_t*)hb)[1] = h1;
    ((uint32_t*)lb)[0] = l0; ((uint32_t*)lb)[1] = l1;
}

__device__ __forceinline__ void ldsm4(uint32_t* r, const __nv_bfloat16* p) {
    uint32_t a = (uint32_t)__cvta_generic_to_shared(p);
    asm volatile("ldmatrix.sync.aligned.m8n8.x4.shared.b16 {%0,%1,%2,%3}, [%4];"
        : "=r"(r[0]), "=r"(r[1]), "=r"(r[2]), "=r"(r[3]) : "r"(a));
}
__device__ __forceinline__ void ldsm4a(uint32_t* r, uint32_t a) {
    asm volatile("ldmatrix.sync.aligned.m8n8.x4.shared.b16 {%0,%1,%2,%3}, [%4];"
        : "=r"(r[0]), "=r"(r[1]), "=r"(r[2]), "=r"(r[3]) : "r"(a));
}
__device__ __forceinline__ void ldsm4ta(uint32_t* r, uint32_t a) {
    asm volatile("ldmatrix.sync.aligned.m8n8.x4.trans.shared.b16 {%0,%1,%2,%3}, [%4];"
        : "=r"(r[0]), "=r"(r[1]), "=r"(r[2]), "=r"(r[3]) : "r"(a));
}
__device__ __forceinline__ void mma16816(float* d, const uint32_t* a,
                                         uint32_t b0, uint32_t b1) {
    asm volatile(
        "mma.sync.aligned.m16n8k16.row.col.f32.bf16.bf16.f32 "
        "{%0,%1,%2,%3},{%4,%5,%6,%7},{%8,%9},{%0,%1,%2,%3};"
        : "+f"(d[0]), "+f"(d[1]), "+f"(d[2]), "+f"(d[3])
        : "r"(a[0]), "r"(a[1]), "r"(a[2]), "r"(a[3]), "r"(b0), "r"(b1));
}
__device__ __forceinline__ void cpa16(uint32_t dst, const void* src) {
    asm volatile("cp.async.cg.shared.global [%0], [%1], 16;\n" :: "r"(dst), "l"(src));
}
__device__ __forceinline__ void cp_commit() {
    asm volatile("cp.async.commit_group;\n");
}
template<int N> __device__ __forceinline__ void cp_wait() {
    asm volatile("cp.async.wait_group %0;\n" :: "n"(N));
}
__device__ __forceinline__ uint32_t aswz(uint32_t o) { return o ^ ((o >> 3) & 0x70); }

// ---------------------------------------------------------------------------
// GEMM (R2/R9 measured-best): out = A(4096x1024) @ W^T + bias, bf16x3.
// fp32 global loads + register prefetch, in-kernel hi/lo split to smem.
// Block 128x128, BK=32, 8 warps (2x4), warp tile 64x32. GST=40 padded rows.
// mode 0/1/2: write split hi/lo Q/K/V head layout (mode 0 pre-scales by log2e
// for the base-2 softmax). mode 3: A=g_ctx, +resid.
// ---------------------------------------------------------------------------
#define GST 40

__global__ void __launch_bounds__(256) gemm_mma(
    const float* __restrict__ A, const float* __restrict__ W,
    const float* __restrict__ bias, const float* __restrict__ resid,
    float* __restrict__ out, int mode)
{
    __shared__ __nv_bfloat16 sAh[128*GST], sAl[128*GST];
    __shared__ __nv_bfloat16 sBh[128*GST], sBl[128*GST];

    const int tid  = threadIdx.x;
    const int lane = tid & 31;
    const int wid  = tid >> 5;
    const int wm   = (wid >> 2) * 64;
    const int wn   = (wid & 3) * 32;
    const int row0 = blockIdx.y * 128;
    const int col0 = blockIdx.x * 128;
    const int lrow = lane & 15;
    const int lcol = (lane >> 4) * 8;

    const float* Ap = (mode >= 3) ? g_ctx : A;
    __nv_bfloat16 *Oh = (mode == 0) ? g_Qh : (mode == 1) ? g_Kh : g_Vh;
    __nv_bfloat16 *Ol = (mode == 0) ? g_Ql : (mode == 1) ? g_Kl : g_Vl;

    float acc[4][4][4] = {};

    const int lr = tid >> 3;          // 0..31
    const int lc = (tid & 7) * 4;     // 0..28

    // prefetch tile 0
    float4 av[4], bv[4];
    #pragma unroll
    for (int p = 0; p < 4; p++) {
        av[p] = *(const float4*)&Ap[(size_t)(row0 + lr + p*32) * DMODEL + lc];
        bv[p] = *(const float4*)&W [(size_t)(col0 + lr + p*32) * DMODEL + lc];
    }

    for (int k0 = 0; k0 < DMODEL; k0 += 32) {
        __syncthreads();
        #pragma unroll
        for (int p = 0; p < 4; p++) {
            int r = lr + p*32;
            cvt_store(&sAh[r*GST + lc], &sAl[r*GST + lc], av[p]);
            cvt_store(&sBh[r*GST + lc], &sBl[r*GST + lc], bv[p]);
        }
        __syncthreads();

        if (k0 + 32 < DMODEL) {
            #pragma unroll
            for (int p = 0; p < 4; p++) {
                av[p] = *(const float4*)&Ap[(size_t)(row0 + lr + p*32) * DMODEL + k0 + 32 + lc];
                bv[p] = *(const float4*)&W [(size_t)(col0 + lr + p*32) * DMODEL + k0 + 32 + lc];
            }
        }

        #pragma unroll
        for (int ks = 0; ks < 2; ks++) {
            uint32_t ah[4][4], al[4][4], bh[2][4], bl[2][4];
            #pragma unroll
            for (int im = 0; im < 4; im++) {
                int off = (wm + im*16 + lrow) * GST + ks*16 + lcol;
                ldsm4(ah[im], &sAh[off]);
                ldsm4(al[im], &sAl[off]);
            }
            #pragma unroll
            for (int g = 0; g < 2; g++) {
                int off = (wn + g*16 + lrow) * GST + ks*16 + lcol;
                ldsm4(bh[g], &sBh[off]);
                ldsm4(bl[g], &sBl[off]);
            }
            #pragma unroll
            for (int im = 0; im < 4; im++)
                #pragma unroll
                for (int jn = 0; jn < 4; jn++) {
                    int g = jn >> 1, o = jn & 1;
                    mma16816(acc[im][jn], ah[im], bh[g][o], bh[g][o+2]);
                    mma16816(acc[im][jn], ah[im], bl[g][o], bl[g][o+2]);
                    mma16816(acc[im][jn], al[im], bh[g][o], bh[g][o+2]);
                }
        }
    }

    const float qsc = (mode == 0) ? LOG2E : 1.0f;

    #pragma unroll
    for (int im = 0; im < 4; im++) {
        #pragma unroll
        for (int jn = 0; jn < 4; jn++) {
            int rg = row0 + wm + im * 16 + (lane >> 2);
            int cg = col0 + wn + jn * 8 + (lane & 3) * 2;
            float v0 = acc[im][jn][0] + bias[cg];
            float v1 = acc[im][jn][1] + bias[cg+1];
            float v2 = acc[im][jn][2] + bias[cg];
            float v3 = acc[im][jn][3] + bias[cg+1];
            if (mode < 3) {
                v0 *= qsc; v1 *= qsc; v2 *= qsc; v3 *= qsc;
                int s0 = rg >> 1, b0b = rg & 1;
                int s1 = (rg + 8) >> 1, b1b = (rg + 8) & 1;
                int h = cg >> 6, dj = cg & 63;
                size_t o0 = (((size_t)b0b * NHEAD + h) * S_LEN + s0) * DHEAD + dj;
                size_t o1 = (((size_t)b1b * NHEAD + h) * S_LEN + s1) * DHEAD + dj;
                uint32_t lo;
                uint32_t hi = split2t(v0, v1, lo);
                *(uint32_t*)&Oh[o0] = hi; *(uint32_t*)&Ol[o0] = lo;
                hi = split2t(v2, v3, lo);
                *(uint32_t*)&Oh[o1] = hi; *(uint32_t*)&Ol[o1] = lo;
            } else {
                const float* rr0 = &resid[(size_t)rg * DMODEL + cg];
                const float* rr1 = &resid[(size_t)(rg+8) * DMODEL + cg];
                *(float2*)&out[(size_t)rg * DMODEL + cg]     = make_float2(v0 + rr0[0], v1 + rr0[1]);
                *(float2*)&out[(size_t)(rg+8) * DMODEL + cg] = make_float2(v2 + rr1[0], v3 + rr1[1]);
            }
        }
    }
}

// ---------------------------------------------------------------------------
// Flash attention: bf16x3, 3-stage cp.async KV pipeline, one sync per tile,
// Q frags in registers, online softmax in BASE-2 (Q pre-scaled by log2e, bare
// ex2), truncation-split P packing. 2 CTAs/SM.
// ---------------------------------------------------------------------------
#define A_ARR   8192u
#define A_STAGE (4u*A_ARR)
#define ATTN_SMEM (3*A_STAGE)          // 98304
#define A_NT 32

__global__ void __launch_bounds__(256,2) attn_mma()
{
    extern __shared__ __nv_bfloat16 sa_mem[];
    const uint32_t smb = (uint32_t)__cvta_generic_to_shared(sa_mem);

    const int tid  = threadIdx.x;
    const int lane = tid & 31;
    const int wid  = tid >> 5;
    const int wm   = wid * 16;
    const int n    = blockIdx.y;
    const int q0   = blockIdx.x * 128;
    const int lrow = lane & 15;
    const int lcolb = ((lane >> 4) * 8) * 2;

    const size_t hofs = (size_t)n * S_LEN * DHEAD;
    const __nv_bfloat16* Qh_g = g_Qh + hofs;
    const __nv_bfloat16* Ql_g = g_Ql + hofs;
    const __nv_bfloat16* srcs[4] = {g_Kh + hofs, g_Kl + hofs, g_Vh + hofs, g_Vl + hofs};

    const int rw = tid >> 2;
    const int qc = tid & 3;

    // Q fragments in registers
    uint32_t qh[4][4], ql[4][4];
    {
        const int qr = q0 + wm + (lane >> 2);
        const int qcc = (lane & 3) * 2;
        #pragma unroll
        for (int kk = 0; kk < 4; kk++) {
            size_t b0 = (size_t)qr * DHEAD + kk * 16 + qcc;
            qh[kk][0] = *(const uint32_t*)&Qh_g[b0];
            qh[kk][1] = *(const uint32_t*)&Qh_g[b0 + 8*DHEAD];
            qh[kk][2] = *(const uint32_t*)&Qh_g[b0 + 8];
            qh[kk][3] = *(const uint32_t*)&Qh_g[b0 + 8*DHEAD + 8];
            ql[kk][0] = *(const uint32_t*)&Ql_g[b0];
            ql[kk][1] = *(const uint32_t*)&Ql_g[b0 + 8*DHEAD];
            ql[kk][2] = *(const uint32_t*)&Ql_g[b0 + 8];
            ql[kk][3] = *(const uint32_t*)&Ql_g[b0 + 8*DHEAD + 8];
        }
    }

    float ctx[8][4] = {};
    float m0 = -1e30f, m1 = -1e30f, l0 = 0.0f, l1 = 0.0f;

    // prologue: stages 0,1
    #pragma unroll
    for (int st = 0; st < 2; st++) {
        #pragma unroll
        for (int a = 0; a < 4; a++) {
            const __nv_bfloat16* p = srcs[a] + (size_t)(st * 64 + rw) * DHEAD;
            uint32_t ab = (uint32_t)st * A_STAGE + (uint32_t)a * A_ARR + (uint32_t)rw * 128;
            #pragma unroll
            for (int j = 0; j < 2; j++) {
                int c16 = qc * 2 + j;
                cpa16(smb + ab + (uint32_t)((c16 ^ (rw & 7)) * 16), p + c16 * 8);
            }
        }
        cp_commit();
    }

    for (int t = 0; t < A_NT; t++) {
        cp_wait<1>();
        __syncthreads();

        if (t + 2 < A_NT) {
            int st = t + 2, slot = st % 3;
            #pragma unroll
            for (int a = 0; a < 4; a++) {
                const __nv_bfloat16* p = srcs[a] + (size_t)(st * 64 + rw) * DHEAD;
                uint32_t ab = (uint32_t)slot * A_STAGE + (uint32_t)a * A_ARR + (uint32_t)rw * 128;
                #pragma unroll
                for (int j = 0; j < 2; j++) {
                    int c16 = qc * 2 + j;
                    cpa16(smb + ab + (uint32_t)((c16 ^ (rw & 7)) * 16), p + c16 * 8);
                }
            }
        }
        cp_commit();

        const uint32_t sb = smb + (uint32_t)(t % 3) * A_STAGE;

        // S' = (Q*log2e) @ K^T   (scores already in base-2 domain)
        float sa[8][4] = {};
        #pragma unroll
        for (int kk = 0; kk < 4; kk++) {
            #pragma unroll
            for (int g = 0; g < 4; g++) {
                uint32_t khf[4], klf[4];
                uint32_t o = (uint32_t)(g * 16 + lrow) * 128 + kk * 32 + lcolb;
                ldsm4a(khf, sb + 0 * A_ARR + aswz(o));
                ldsm4a(klf, sb + 1 * A_ARR + aswz(o));
                #pragma unroll
                for (int o2 = 0; o2 < 2; o2++) {
                    mma16816(sa[2*g+o2], qh[kk], khf[o2], khf[o2+2]);
                    mma16816(sa[2*g+o2], qh[kk], klf[o2], klf[o2+2]);
                    mma16816(sa[2*g+o2], ql[kk], khf[o2], khf[o2+2]);
                }
            }
        }

        // Online softmax, base-2: P = 2^(S' - m')
        float mx0 = -1e30f, mx1 = -1e30f;
        #pragma unroll
        for (int jn = 0; jn < 8; jn++) {
            mx0 = fmaxf(mx0, fmaxf(sa[jn][0], sa[jn][1]));
            mx1 = fmaxf(mx1, fmaxf(sa[jn][2], sa[jn][3]));
        }
        mx0 = fmaxf(mx0, __shfl_xor_sync(0xffffffffu, mx0, 1));
        mx0 = fmaxf(mx0, __shfl_xor_sync(0xffffffffu, mx0, 2));
        mx1 = fmaxf(mx1, __shfl_xor_sync(0xffffffffu, mx1, 1));
        mx1 = fmaxf(mx1, __shfl_xor_sync(0xffffffffu, mx1, 2));

        float mn0 = fmaxf(m0, mx0), mn1 = fmaxf(m1, mx1);
        float c0 = ex2f(m0 - mn0), c1 = ex2f(m1 - mn1);
        float s0 = 0.0f, s1 = 0.0f;
        #pragma unroll
        for (int jn = 0; jn < 8; jn++) {
            sa[jn][0] = ex2f(sa[jn][0] - mn0);
            sa[jn][1] = ex2f(sa[jn][1] - mn0);
            sa[jn][2] = ex2f(sa[jn][2] - mn1);
            sa[jn][3] = ex2f(sa[jn][3] - mn1);
            s0 += sa[jn][0] + sa[jn][1];
            s1 += sa[jn][2] + sa[jn][3];
            ctx[jn][0] *= c0; ctx[jn][1] *= c0;
            ctx[jn][2] *= c1; ctx[jn][3] *= c1;
        }
        s0 += __shfl_xor_sync(0xffffffffu, s0, 1);
        s0 += __shfl_xor_sync(0xffffffffu, s0, 2);
        s1 += __shfl_xor_sync(0xffffffffu, s1, 1);
        s1 += __shfl_xor_sync(0xffffffffu, s1, 2);
        l0 = l0 * c0 + s0;  m0 = mn0;
        l1 = l1 * c1 + s1;  m1 = mn1;

        // Pack P fragments via truncation split (QK acc layout == PV A layout)
        uint32_t ph[4][4], pl[4][4];
        #pragma unroll
        for (int kc = 0; kc < 4; kc++) {
            ph[kc][0] = split2t(sa[2*kc][0],   sa[2*kc][1],   pl[kc][0]);
            ph[kc][1] = split2t(sa[2*kc][2],   sa[2*kc][3],   pl[kc][1]);
            ph[kc][2] = split2t(sa[2*kc+1][0], sa[2*kc+1][1], pl[kc][2]);
            ph[kc][3] = split2t(sa[2*kc+1][2], sa[2*kc+1][3], pl[kc][3]);
        }

        // ctx += P @ V   (V natural [kv][dh] via ldsm.trans)
        #pragma unroll
        for (int kc = 0; kc < 4; kc++) {
            #pragma unroll
            for (int g = 0; g < 4; g++) {
                uint32_t vhf[4], vlf[4];
                uint32_t o = (uint32_t)(kc * 16 + lrow) * 128 + g * 32 + lcolb;
                ldsm4ta(vhf, sb + 2 * A_ARR + aswz(o));
                ldsm4ta(vlf, sb + 3 * A_ARR + aswz(o));
                #pragma unroll
                for (int o2 = 0; o2 < 2; o2++) {
                    mma16816(ctx[2*g+o2], ph[kc], vhf[2*o2], vhf[2*o2+1]);
                    mma16816(ctx[2*g+o2], ph[kc], vlf[2*o2], vlf[2*o2+1]);
                    mma16816(ctx[2*g+o2], pl[kc], vhf[2*o2], vhf[2*o2+1]);
                }
            }
        }
    }

    // Finalize: write fp32 ctx (s,b,D)
    const int b = n >> 4, h = n & 15;
    const float inv0 = 1.0f / l0, inv1 = 1.0f / l1;
    const int s0r = q0 + wm + (lane >> 2);
    #pragma unroll
    for (int jn = 0; jn < 8; jn++) {
        int dh = jn * 8 + (lane & 3) * 2;
        size_t o0 = ((size_t)s0r * BATCH + b) * DMODEL + h * DHEAD + dh;
        size_t o1 = ((size_t)(s0r + 8) * BATCH + b) * DMODEL + h * DHEAD + dh;
        *(float2*)&g_ctx[o0] = make_float2(ctx[jn][0] * inv0, ctx[jn][1] * inv0);
        *(float2*)&g_ctx[o1] = make_float2(ctx[jn][2] * inv1, ctx[jn][3] * inv1);
    }
}

// ---------------------------------------------------------------------------
// LayerNorm (in-place): one block per row of 1024
// ---------------------------------------------------------------------------
__device__ __forceinline__ float block_sum256(float v, float* red)
{
    #pragma unroll
    for (int o = 16; o > 0; o >>= 1) v += __shfl_xor_sync(0xffffffffu, v, o);
    if ((threadIdx.x & 31) == 0) red[threadIdx.x >> 5] = v;
    __syncthreads();
    if (threadIdx.x < 32) {
        float x = (threadIdx.x < 8) ? red[threadIdx.x] : 0.0f;
        #pragma unroll
        for (int o = 4; o > 0; o >>= 1) x += __shfl_xor_sync(0xffffffffu, x, o);
        if (threadIdx.x == 0) red[0] = x;
    }
    __syncthreads();
    float rv = red[0];
    __syncthreads();
    return rv;
}

__global__ void __launch_bounds__(256) ln_kernel(
    float* __restrict__ y, const float* __restrict__ w, const float* __restrict__ bb)
{
    __shared__ float red[8];
    const int rix = blockIdx.x;
    float* row = y + (size_t)rix * DMODEL;
    const int tid = threadIdx.x;

    float v[4];
    #pragma unroll
    for (int p = 0; p < 4; p++) v[p] = row[tid + p * 256];

    float s = v[0] + v[1] + v[2] + v[3];
    float mean = block_sum256(s, red) * (1.0f / DMODEL);

    float ss = 0.0f;
    #pragma unroll
    for (int p = 0; p < 4; p++) { float d = v[p] - mean; ss = fmaf(d, d, ss); }
    float var = block_sum256(ss, red) * (1.0f / DMODEL);
    float rstd = rsqrtf(var + 1e-12f);

    #pragma unroll
    for (int p = 0; p < 4; p++) {
        int c = tid + p * 256;
        row[c] = w[c] * (v[p] - mean) * rstd + bb[c];
    }
}

// ---------------------------------------------------------------------------
extern "C" void kernel_launch(void* const* d_in, const int* in_sizes, int n_in,
                              void* d_out, int out_size)
{
    const float* q_in = (const float*)d_in[0];
    const float* k_in = (const float*)d_in[1];
    const float* v_in = (const float*)d_in[2];
    const float* Wq   = (const float*)d_in[3];
    const float* bq   = (const float*)d_in[4];
    const float* Wk   = (const float*)d_in[5];
    const float* bk   = (const float*)d_in[6];
    const float* Wv   = (const float*)d_in[7];
    const float* bv   = (const float*)d_in[8];
    const float* Wo   = (const float*)d_in[9];
    const float* bo   = (const float*)d_in[10];
    const float* ln_w = (const float*)d_in[11];
    const float* ln_b = (const float*)d_in[12];
    float* out = (float*)d_out;

    static int attr_done = 0;
    if (!attr_done) {
        cudaFuncSetAttribute(attn_mma, cudaFuncAttributeMaxDynamicSharedMemorySize, ATTN_SMEM);
        attr_done = 1;
    }

    dim3 gg(DMODEL / 128, MROWS / 128);   // (8, 32)

    gemm_mma<<<gg, 256>>>(q_in, Wq, bq, nullptr, nullptr, 0);
    gemm_mma<<<gg, 256>>>(k_in, Wk, bk, nullptr, nullptr, 1);
    gemm_mma<<<gg, 256>>>(v_in, Wv, bv, nullptr, nullptr, 2);

    attn_mma<<<dim3(S_LEN / 128, BHEADS), 256, ATTN_SMEM>>>();

    gemm_mma<<<gg, 256>>>(nullptr, Wo, bo, q_in, out, 3);

    ln_kernel<<<MROWS, 256>>>(out, ln_w, ln_b);
}